// round 2
// baseline (speedup 1.0000x reference)
#include <cuda_runtime.h>

// YoloLoss: N=4096, S=14, B=2, NUM_CLS=20
// inputs: pred_tensor (N,S,S,30) f32, target_boxes (N,S,S,4) f32,
//         target_cls (N,S,S,20) f32, has_object_map (N,S,S) int32 (bool widened)
// output: 5 f32 = (total, reg, contain_conf, no_obj, cls)

static constexpr int NSAMP = 4096;
static constexpr int S2    = 14 * 14;
static constexpr int NCELL = NSAMP * S2;   // 802816
static constexpr int CPB   = 128;          // cells (== threads) per block
static constexpr int NBLK  = NCELL / CPB;  // 6272

// global accumulators: reg_sum, contain_sum, noobj_sum(raw conf^2), cls_sum
__device__ float g_acc[4];

__global__ void zero_acc_k() {
    if (threadIdx.x < 4) g_acc[threadIdx.x] = 0.0f;
}

__global__ __launch_bounds__(CPB) void yolo_k(
    const float* __restrict__ pred,
    const float* __restrict__ tbox,
    const float* __restrict__ tcls,
    const int* __restrict__ mask)
{
    // padded smem: stride 31 / 21 are odd -> conflict-free strided reads
    __shared__ float sp[CPB * 31];
    __shared__ float sc[CPB * 21];
    __shared__ float red[CPB / 32][4];

    const int tid = threadIdx.x;
    const long base = (long)blockIdx.x * CPB;

    // --- coalesced staging: pred (30 ch/cell) and cls (20 ch/cell) ---
    const float* __restrict__ pg = pred + base * 30;
    const float* __restrict__ cg = tcls + base * 20;
#pragma unroll
    for (int i = 0; i < 30; i++) {
        int idx  = tid + i * CPB;
        int cell = idx / 30;
        int ch   = idx - cell * 30;
        sp[cell * 31 + ch] = pg[idx];
    }
#pragma unroll
    for (int i = 0; i < 20; i++) {
        int idx  = tid + i * CPB;
        int cell = idx / 20;
        int ch   = idx - cell * 20;
        sc[cell * 21 + ch] = cg[idx];
    }
    __syncthreads();

    const long cell = base + tid;
    const float4 tb = reinterpret_cast<const float4*>(tbox)[cell]; // x,y,w,h
    const float  m  = (mask[cell] != 0) ? 1.0f : 0.0f;

    const float* P = &sp[tid * 31];
    const float* C = &sc[tid * 21];

    // classification loss term
    float cls = 0.0f;
#pragma unroll
    for (int k = 0; k < 20; k++) {
        float d = P[10 + k] - C[k];
        cls += d * d;
    }
    cls *= m;

    // no-object confidence term (raw; 0.5 factor applied in finalize)
    float c0 = P[4], c1 = P[9];
    float noobj = (c0 * c0 + c1 * c1) * (1.0f - m);

    // IoU vs target for both boxes
    const float invS = 1.0f / 14.0f;
    float gx1 = tb.x * invS - 0.5f * tb.z, gx2 = tb.x * invS + 0.5f * tb.z;
    float gy1 = tb.y * invS - 0.5f * tb.w, gy2 = tb.y * invS + 0.5f * tb.w;
    float area_g = (gx2 - gx1) * (gy2 - gy1);

    float iou0, iou1;
#pragma unroll
    for (int b = 0; b < 2; b++) {
        float px = P[5 * b + 0], py = P[5 * b + 1];
        float pw = P[5 * b + 2], ph = P[5 * b + 3];
        float px1 = px * invS - 0.5f * pw, px2 = px * invS + 0.5f * pw;
        float py1 = py * invS - 0.5f * ph, py2 = py * invS + 0.5f * ph;
        float iw = fmaxf(fminf(px2, gx2) - fmaxf(px1, gx1), 0.0f);
        float ih = fmaxf(fminf(py2, gy2) - fmaxf(py1, gy1), 0.0f);
        float inter  = iw * ih;
        float area_p = (px2 - px1) * (py2 - py1);
        float v = inter / (area_p + area_g - inter);
        if (b == 0) iou0 = v; else iou1 = v;
    }
    // jnp.argmax returns first max on ties -> strict '>' to pick box 1
    const int best = (iou1 > iou0) ? 1 : 0;
    const float bx = P[5 * best + 0], by = P[5 * best + 1];
    const float bw = P[5 * best + 2], bh = P[5 * best + 3];
    const float bc = P[5 * best + 4];

    float dx = bx - tb.x, dy = by - tb.y;
    float dw = sqrtf(bw) - sqrtf(tb.z);
    float dh = sqrtf(bh) - sqrtf(tb.w);
    float regp = (dx * dx + dy * dy + dw * dw + dh * dh) * m; // L_COORD in finalize
    float dc = bc - 1.0f;
    float contain = dc * dc * m;

    // --- reduction: warp shuffle -> smem -> one atomic per quantity/block ---
    float v0 = regp, v1 = contain, v2 = noobj, v3 = cls;
#pragma unroll
    for (int off = 16; off > 0; off >>= 1) {
        v0 += __shfl_xor_sync(0xffffffffu, v0, off);
        v1 += __shfl_xor_sync(0xffffffffu, v1, off);
        v2 += __shfl_xor_sync(0xffffffffu, v2, off);
        v3 += __shfl_xor_sync(0xffffffffu, v3, off);
    }
    const int warp = tid >> 5;
    if ((tid & 31) == 0) {
        red[warp][0] = v0; red[warp][1] = v1;
        red[warp][2] = v2; red[warp][3] = v3;
    }
    __syncthreads();
    if (tid < 4) {
        float s = 0.0f;
#pragma unroll
        for (int w = 0; w < CPB / 32; w++) s += red[w][tid];
        atomicAdd(&g_acc[tid], s);
    }
}

__global__ void finalize_k(float* __restrict__ out) {
    const float invN = 1.0f / (float)NSAMP;
    float reg     = 5.0f * g_acc[0] * invN;
    float contain = g_acc[1] * invN;
    float noobj   = 0.5f * g_acc[2] * invN;
    float cls     = g_acc[3] * invN;
    out[0] = reg + contain + noobj + cls;
    out[1] = reg;
    out[2] = contain;
    out[3] = noobj;
    out[4] = cls;
}

extern "C" void kernel_launch(void* const* d_in, const int* in_sizes, int n_in,
                              void* d_out, int out_size)
{
    const float* pred = (const float*)d_in[0];
    const float* tbox = (const float*)d_in[1];
    const float* tcls = (const float*)d_in[2];
    const int*   mask = (const int*)d_in[3];
    float* out = (float*)d_out;

    zero_acc_k<<<1, 32>>>();
    yolo_k<<<NBLK, CPB>>>(pred, tbox, tcls, mask);
    finalize_k<<<1, 1>>>(out);
}